// round 1
// baseline (speedup 1.0000x reference)
#include <cuda_runtime.h>

// Grouped 3-tap width conv with cyclic rolls, fp32, split-K over input channels.
//
// y[o,k,n,m] = sum_{i,j} t[o,i,n,m+j-1] * w[i,k,j]   (zero padded window)
//   t[o,i,n,m] = x[o*512+i, n, (m-1) mod 7]          (width roll +1)
//   out[o*512+k, (n+1) mod 7, m] = y[o,k,n,m]        (height roll +1)

#define S_SPLITS 8
#define CI       64      // 512 / S_SPLITS input channels per block
#define TK       16      // output channels per block
#define NKT      32      // 512 / TK k-tiles
#define ROWS     14      // 2 groups * 7 heights
#define THREADS  (TK * ROWS)   // 224

__device__ float g_scratch[S_SPLITS * 1024 * 49];

__global__ __launch_bounds__(THREADS) void conv_part(const float* __restrict__ x,
                                                     const float* __restrict__ w)
{
    __shared__ float sIn[CI][ROWS][8];   // [i][o*7+n][m], col 7 = zero pad
    __shared__ float sW[CI][TK * 4];     // [i][kl*4 + j], j=3 pad = 0

    const int tid   = threadIdx.x;
    const int k0    = blockIdx.x * TK;
    const int s     = blockIdx.y;
    const int iBase = s * CI;

    // ---- stage input slab (both groups) with the width roll baked in ----
    for (int e = tid; e < 2 * CI * 49; e += THREADS) {
        int o  = e / (CI * 49);
        int r  = e - o * (CI * 49);
        int i  = r / 49;
        int p  = r - i * 49;
        int n  = p / 7;
        int mw = p - n * 7;
        float v = x[(o * 512 + iBase + i) * 49 + p];
        int m = mw + 1; if (m == 7) m = 0;   // roll(+1) along width
        sIn[i][o * 7 + n][m] = v;
    }
    for (int e = tid; e < CI * ROWS; e += THREADS)
        sIn[e / ROWS][e - (e / ROWS) * ROWS][7] = 0.0f;

    // ---- stage weight tile, padded to float4 ----
    for (int e = tid; e < CI * TK * 3; e += THREADS) {
        int i  = e / (TK * 3);
        int q  = e - i * (TK * 3);
        int kl = q / 3;
        int j  = q - kl * 3;
        sW[i][kl * 4 + j] = w[(iBase + i) * 1536 + (k0 + kl) * 3 + j];
    }
    for (int e = tid; e < CI * TK; e += THREADS)
        sW[e / TK][(e - (e / TK) * TK) * 4 + 3] = 0.0f;

    __syncthreads();

    // ---- compute: thread = (output channel lane kl, (group o, height n)) ----
    const int kl  = tid / ROWS;
    const int row = tid - kl * ROWS;     // row = o*7 + n
    const int o   = row / 7;
    const int n   = row - o * 7;

    float acc[7];
#pragma unroll
    for (int m = 0; m < 7; m++) acc[m] = 0.0f;

    const float4* pin = reinterpret_cast<const float4*>(&sIn[0][row][0]); // stride 28 f4 per i
    const float4* pw  = reinterpret_cast<const float4*>(&sW[0][kl * 4]);  // stride 16 f4 per i

#pragma unroll 4
    for (int i = 0; i < CI; i++) {
        float4 lo = pin[i * 28];        // r0..r3
        float4 hi = pin[i * 28 + 1];    // r4..r6, pad0
        float4 wv = pw[i * TK];         // w0,w1,w2,pad

        // center tap j=1: acc[m] += r[m]*w1
        acc[0] += lo.x * wv.y; acc[1] += lo.y * wv.y; acc[2] += lo.z * wv.y;
        acc[3] += lo.w * wv.y; acc[4] += hi.x * wv.y; acc[5] += hi.y * wv.y;
        acc[6] += hi.z * wv.y;
        // left tap j=0: acc[m] += r[m-1]*w0  (m=0 hits pad, skipped)
        acc[1] += lo.x * wv.x; acc[2] += lo.y * wv.x; acc[3] += lo.z * wv.x;
        acc[4] += lo.w * wv.x; acc[5] += hi.x * wv.x; acc[6] += hi.y * wv.x;
        // right tap j=2: acc[m] += r[m+1]*w2  (m=6 hits pad, skipped)
        acc[0] += lo.y * wv.z; acc[1] += lo.z * wv.z; acc[2] += lo.w * wv.z;
        acc[3] += hi.x * wv.z; acc[4] += hi.y * wv.z; acc[5] += hi.z * wv.z;
    }

    // ---- write partials (no atomics; deterministic reduce in kernel 2) ----
    const int co = o * 512 + k0 + kl;
    float* dst = &g_scratch[(s * 1024 + co) * 49 + n * 7];
#pragma unroll
    for (int m = 0; m < 7; m++) dst[m] = acc[m];
}

__global__ __launch_bounds__(256) void reduce_out(float* __restrict__ out)
{
    int e = blockIdx.x * blockDim.x + threadIdx.x;
    if (e >= 1024 * 49) return;
    float sum = 0.0f;
#pragma unroll
    for (int s = 0; s < S_SPLITS; s++)
        sum += g_scratch[s * 1024 * 49 + e];
    int c = e / 49;
    int p = e - c * 49;
    int n = p / 7;
    int m = p - n * 7;
    int nOut = n + 1; if (nOut == 7) nOut = 0;   // height roll +1
    out[c * 49 + nOut * 7 + m] = sum;
}

extern "C" void kernel_launch(void* const* d_in, const int* in_sizes, int n_in,
                              void* d_out, int out_size)
{
    const float* x = (const float*)d_in[0];
    const float* w = (const float*)d_in[1];
    float* out = (float*)d_out;

    conv_part<<<dim3(NKT, S_SPLITS), THREADS>>>(x, w);
    reduce_out<<<(1024 * 49 + 255) / 256, 256>>>(out);
}

// round 2
// speedup vs baseline: 1.2358x; 1.2358x over previous
#include <cuda_runtime.h>

// Grouped 3-tap width conv with cyclic rolls, fp32, split-K over input channels.
//
// y[o,k,n,m] = sum_{i,j} t[o,i,n,m+j-1] * w[i,k,j]   (zero padded window)
//   t[o,i,n,m] = x[o*512+i, n, (m-1) mod 7]          (width roll +1)
//   out[o*512+k, (n+1) mod 7, m] = y[o,k,n,m]        (height roll +1, baked into partial write)

#define S_SPLITS 8
#define CI       64              // 512 / S_SPLITS input channels per block
#define TK       32              // output channels per block (one warp-lane each)
#define NKT      16              // 512 / TK k-tiles
#define ROWS     14              // 2 groups * 7 heights; one warp per row
#define THREADS  (ROWS * 32)     // 448

__device__ float g_scratch[S_SPLITS * 1024 * 49];   // partials, already height-rolled

__global__ __launch_bounds__(THREADS) void conv_part(const float* __restrict__ x,
                                                     const float* __restrict__ w)
{
    __shared__ float sIn[CI][ROWS][8];   // [i][o*7+n][m], col 7 = zero pad
    __shared__ float sW[CI][TK * 4];     // [i][kl*4 + j], j=3 pad = 0

    const int tid   = threadIdx.x;
    const int k0    = blockIdx.x * TK;
    const int s     = blockIdx.y;
    const int iBase = s * CI;

    // ---- stage input slab (both groups) with the width roll baked in ----
    for (int e = tid; e < 2 * CI * 49; e += THREADS) {
        int o  = e / (CI * 49);
        int r  = e - o * (CI * 49);
        int i  = r / 49;
        int p  = r - i * 49;
        int n  = p / 7;
        int mw = p - n * 7;
        float v = x[(o * 512 + iBase + i) * 49 + p];
        int m = mw + 1; if (m == 7) m = 0;   // roll(+1) along width
        sIn[i][o * 7 + n][m] = v;
    }
    for (int e = tid; e < CI * ROWS; e += THREADS)
        sIn[e / ROWS][e - (e / ROWS) * ROWS][7] = 0.0f;

    // ---- stage weight tile, padded to float4 ----
    for (int e = tid; e < CI * TK * 3; e += THREADS) {
        int i  = e / (TK * 3);
        int q  = e - i * (TK * 3);
        int kl = q / 3;
        int j  = q - kl * 3;
        sW[i][kl * 4 + j] = w[(iBase + i) * 1536 + (k0 + kl) * 3 + j];
    }
    for (int e = tid; e < CI * TK; e += THREADS)
        sW[e / TK][(e - (e / TK) * TK) * 4 + 3] = 0.0f;

    __syncthreads();

    // ---- compute: warp = (group o, height n) row; lane = output channel ----
    const int warp = tid >> 5;          // 0..13 = o*7 + n
    const int lane = tid & 31;          // kl
    const int o    = warp / 7;
    const int n    = warp - o * 7;

    float acc[7];
#pragma unroll
    for (int m = 0; m < 7; m++) acc[m] = 0.0f;

    // input row: broadcast across the warp (all lanes same address -> conflict-free N=1)
    const float4* pin = reinterpret_cast<const float4*>(&sIn[0][warp][0]); // stride 28 f4 / i
    // weight: 16B/lane stride -> conflict-free at the 4-cyc structural floor
    const float4* pw  = reinterpret_cast<const float4*>(&sW[0][lane * 4]); // stride 32 f4 / i

#pragma unroll 4
    for (int i = 0; i < CI; i++) {
        float4 lo = pin[i * 28];        // r0..r3
        float4 hi = pin[i * 28 + 1];    // r4..r6, pad0
        float4 wv = pw[i * 32];         // w0,w1,w2,pad

        // center tap j=1
        acc[0] += lo.x * wv.y; acc[1] += lo.y * wv.y; acc[2] += lo.z * wv.y;
        acc[3] += lo.w * wv.y; acc[4] += hi.x * wv.y; acc[5] += hi.y * wv.y;
        acc[6] += hi.z * wv.y;
        // left tap j=0 (m=0 would hit pad, skipped)
        acc[1] += lo.x * wv.x; acc[2] += lo.y * wv.x; acc[3] += lo.z * wv.x;
        acc[4] += lo.w * wv.x; acc[5] += hi.x * wv.x; acc[6] += hi.y * wv.x;
        // right tap j=2 (m=6 would hit pad, skipped)
        acc[0] += lo.y * wv.z; acc[1] += lo.z * wv.z; acc[2] += lo.w * wv.z;
        acc[3] += hi.x * wv.z; acc[4] += hi.y * wv.z; acc[5] += hi.z * wv.z;
    }

    // ---- write partials at FINAL output index (height roll baked in) ----
    const int co   = o * 512 + k0 + lane;
    int nOut = n + 1; if (nOut == 7) nOut = 0;
    float* dst = &g_scratch[(s * 1024 + co) * 49 + nOut * 7];
#pragma unroll
    for (int m = 0; m < 7; m++) dst[m] = acc[m];
}

// identity-indexed float4 reduction over the split dimension
__global__ __launch_bounds__(256) void reduce_out(float* __restrict__ out)
{
    const int e = blockIdx.x * 256 + threadIdx.x;        // float4 index, 12544 total
    const float4* sc = reinterpret_cast<const float4*>(g_scratch);
    float4 sum = sc[e];
#pragma unroll
    for (int s = 1; s < S_SPLITS; s++) {
        float4 v = sc[s * (1024 * 49 / 4) + e];
        sum.x += v.x; sum.y += v.y; sum.z += v.z; sum.w += v.w;
    }
    reinterpret_cast<float4*>(out)[e] = sum;
}

extern "C" void kernel_launch(void* const* d_in, const int* in_sizes, int n_in,
                              void* d_out, int out_size)
{
    const float* x = (const float*)d_in[0];
    const float* w = (const float*)d_in[1];
    float* out = (float*)d_out;

    conv_part<<<dim3(NKT, S_SPLITS), THREADS>>>(x, w);
    reduce_out<<<1024 * 49 / 4 / 256, 256>>>(out);     // 49 blocks
}

// round 3
// speedup vs baseline: 1.2405x; 1.0038x over previous
#include <cuda_runtime.h>

// Grouped 3-tap width conv with cyclic rolls, fp32.
// Single fused kernel: split-K partials -> global spin barrier -> distributed reduce.
// Mainloop uses packed fma.rn.f32x2 (Blackwell FFMA2): lane computes output
// channels (k, k+32) as a 64-bit pair.
//
// y[o,k,n,m] = sum_{i,j} f[o,i,n,m+j] * w[i,k,j],  f[u] = r[u-1] zero-padded,
// r = width-rolled x; height roll baked into the partial-write index.

#define S_SPLITS 16
#define CI       32              // 512 / S_SPLITS input channels per block
#define TK       64              // output channels per block: 32 lanes x 2 (k, k+32)
#define NKT      8               // 512 / TK
#define ROWS     14              // 2 groups * 7 heights; one warp per row
#define THREADS  (ROWS * 32)     // 448
#define NBLOCKS  (NKT * S_SPLITS) // 128 <= 148 SMs -> all co-resident

typedef unsigned long long ull;

__device__ float2   g_scr[S_SPLITS * 2 * NKT * 32 * 49];  // paired partials, 3.2 MB
__device__ unsigned g_bar_arrive;   // zero-init, self-resetting
__device__ unsigned g_bar_depart;

__device__ __forceinline__ ull ffma2(ull a, ull b, ull c)
{
    ull d;
    asm("fma.rn.f32x2 %0, %1, %2, %3;" : "=l"(d) : "l"(a), "l"(b), "l"(c));
    return d;
}

__global__ __launch_bounds__(THREADS) void conv_fused(const float* __restrict__ x,
                                                      const float* __restrict__ w,
                                                      float* __restrict__ out)
{
    __shared__ float2     sInd[CI][ROWS][10];  // dup pairs (f_u,f_u), u=0..8, [9]=pad. 35840 B
    __shared__ ulonglong2 sWa[CI][32];         // (w0_k,w0_k32),(w1_k,w1_k32)        16384 B
    __shared__ ull        sWb[CI][32];         // (w2_k,w2_k32)                       8192 B

    const int tid   = threadIdx.x;
    const int kb    = blockIdx.x;          // 0..7
    const int s     = blockIdx.y;          // 0..15
    const int k0    = kb * TK;
    const int iBase = s * CI;

    // ---- zero-pad entries u in {0,8,9} (disjoint from value writes, no sync needed) ----
    for (int e = tid; e < CI * ROWS * 3; e += THREADS) {
        int i = e / (ROWS * 3);
        int r = e - i * (ROWS * 3);
        int row = r / 3;
        int z = r - row * 3;                    // 0,1,2 -> u = 0,8,9
        int u = (z == 0) ? 0 : (7 + z);
        sInd[i][row][u] = make_float2(0.f, 0.f);
    }

    // ---- stage input slab, width roll baked in, duplicated pairs ----
    for (int e = tid; e < 2 * CI * 49; e += THREADS) {
        int o  = e / (CI * 49);
        int r  = e - o * (CI * 49);
        int i  = r / 49;
        int p  = r - i * 49;
        int n  = p / 7;
        int mw = p - n * 7;
        float v = x[(o * 512 + iBase + i) * 49 + p];
        int m = mw + 1; if (m == 7) m = 0;      // width roll +1
        sInd[i][o * 7 + n][m + 1] = make_float2(v, v);   // f[u] = r[u-1]
    }

    // ---- stage weight pairs: lane kl owns (k0+kl, k0+32+kl) ----
    for (int e = tid; e < CI * 32 * 3; e += THREADS) {
        int i  = e / (32 * 3);
        int q  = e - i * (32 * 3);
        int kl = q / 3;
        int j  = q - kl * 3;
        float wa = w[(iBase + i) * 1536 + (k0 + kl) * 3 + j];
        float wb = w[(iBase + i) * 1536 + (k0 + 32 + kl) * 3 + j];
        if (j == 2) {
            float2 p2 = make_float2(wa, wb);
            sWb[i][kl] = *reinterpret_cast<ull*>(&p2);
        } else {
            float* dst = reinterpret_cast<float*>(&sWa[i][kl]);
            dst[j * 2 + 0] = wa;
            dst[j * 2 + 1] = wb;
        }
    }

    __syncthreads();

    // ---- compute: warp = (o,n) row; lane = k-pair ----
    const int warp = tid >> 5;       // 0..13 = o*7+n
    const int lane = tid & 31;
    const int o    = warp / 7;
    const int n    = warp - o * 7;

    ull A[7];
#pragma unroll
    for (int m = 0; m < 7; m++) A[m] = 0ull;

#pragma unroll 4
    for (int i = 0; i < CI; i++) {
        const ulonglong2* pr = reinterpret_cast<const ulonglong2*>(&sInd[i][warp][0]);
        ulonglong2 L0 = pr[0];   // p0,p1   (broadcast LDS.128)
        ulonglong2 L1 = pr[1];   // p2,p3
        ulonglong2 L2 = pr[2];   // p4,p5
        ulonglong2 L3 = pr[3];   // p6,p7
        ulonglong2 L4 = pr[4];   // p8,pad
        ulonglong2 W01 = sWa[i][lane];
        ull        W2  = sWb[i][lane];
        ull p0 = L0.x, p1 = L0.y, p2 = L1.x, p3 = L1.y;
        ull p4 = L2.x, p5 = L2.y, p6 = L3.x, p7 = L3.y, p8 = L4.x;

        // A[m] += p[m]*w0 + p[m+1]*w1 + p[m+2]*w2
        A[0] = ffma2(p0, W01.x, A[0]); A[0] = ffma2(p1, W01.y, A[0]); A[0] = ffma2(p2, W2, A[0]);
        A[1] = ffma2(p1, W01.x, A[1]); A[1] = ffma2(p2, W01.y, A[1]); A[1] = ffma2(p3, W2, A[1]);
        A[2] = ffma2(p2, W01.x, A[2]); A[2] = ffma2(p3, W01.y, A[2]); A[2] = ffma2(p4, W2, A[2]);
        A[3] = ffma2(p3, W01.x, A[3]); A[3] = ffma2(p4, W01.y, A[3]); A[3] = ffma2(p5, W2, A[3]);
        A[4] = ffma2(p4, W01.x, A[4]); A[4] = ffma2(p5, W01.y, A[4]); A[4] = ffma2(p6, W2, A[4]);
        A[5] = ffma2(p5, W01.x, A[5]); A[5] = ffma2(p6, W01.y, A[5]); A[5] = ffma2(p7, W2, A[5]);
        A[6] = ffma2(p6, W01.x, A[6]); A[6] = ffma2(p7, W01.y, A[6]); A[6] = ffma2(p8, W2, A[6]);
    }

    // ---- write paired partials, height roll baked in ----
    int nOut = n + 1; if (nOut == 7) nOut = 0;
    {
        float2* dst = &g_scr[((((s * 2 + o) * NKT + kb) * 32 + lane) * 49) + nOut * 7];
#pragma unroll
        for (int m = 0; m < 7; m++) dst[m] = *reinterpret_cast<float2*>(&A[m]);
    }

    // ---- grid-wide barrier (all 128 blocks co-resident) ----
    __threadfence();
    __syncthreads();
    if (tid == 0) {
        atomicAdd(&g_bar_arrive, 1u);
        while (*(volatile unsigned*)&g_bar_arrive < NBLOCKS) __nanosleep(64);
    }
    __syncthreads();

    // ---- distributed reduce: 25088 entries of (o,kb',kl,q), each -> 2 outputs ----
    int gid = blockIdx.y * (NKT * THREADS) + blockIdx.x * THREADS + tid;
    if (gid < 2 * NKT * 32 * 49) {
        int q  = gid % 49;
        int r  = gid / 49;
        int kl = r & 31;  r >>= 5;
        int kc = r & (NKT - 1);
        int oo = r >> 3;
        float2 sum = make_float2(0.f, 0.f);
#pragma unroll
        for (int sp = 0; sp < S_SPLITS; sp++) {
            float2 v = __ldcg(&g_scr[((((sp * 2 + oo) * NKT + kc) * 32 + kl) * 49) + q]);
            sum.x += v.x; sum.y += v.y;
        }
        int c = oo * 512 + kc * TK + kl;
        out[c * 49 + q]        = sum.x;
        out[(c + 32) * 49 + q] = sum.y;
    }

    // ---- reset barrier for next graph replay (deterministic) ----
    __syncthreads();
    if (tid == 0) {
        unsigned t = atomicAdd(&g_bar_depart, 1u);
        if (t == NBLOCKS - 1) {
            g_bar_arrive = 0;
            __threadfence();
            g_bar_depart = 0;
        }
    }
}

extern "C" void kernel_launch(void* const* d_in, const int* in_sizes, int n_in,
                              void* d_out, int out_size)
{
    const float* x = (const float*)d_in[0];
    const float* w = (const float*)d_in[1];
    float* out = (float*)d_out;

    conv_fused<<<dim3(NKT, S_SPLITS), THREADS>>>(x, w, out);
}

// round 4
// speedup vs baseline: 1.2429x; 1.0019x over previous
#include <cuda_runtime.h>

// Grouped 3-tap width conv with cyclic rolls, fp32.
// Single fused kernel: intra-block i-split (2 halves) + split-K over blocks,
// global spin barrier, distributed reduce. Mainloop uses packed fma.rn.f32x2.
//
// y[o,k,n,m] = sum_{i,j} f[o,i,n,m+j] * w[i,k,j],  f[u] = r[u-1] zero-padded,
// r = width-rolled x; height roll baked into the partial-write index.

#define S_SPLITS 16
#define CI       32              // 512 / S_SPLITS input channels per block
#define CIH      (CI / 2)        // per-warp-half i count
#define TK       64              // output channels per block: 32 lanes x 2 (k, k+32)
#define NKT      8               // 512 / TK
#define ROWS     14              // 2 groups * 7 heights
#define WARPS    (ROWS * 2)      // 28: warp = (row, i-half)
#define THREADS  (WARPS * 32)    // 896
#define NBLOCKS  (NKT * S_SPLITS) // 128 <= 148 SMs -> all co-resident (1 block/SM)

typedef unsigned long long ull;

__device__ float2   g_scr[S_SPLITS * 2 * NKT * 32 * 49];  // paired partials
__device__ unsigned g_bar_arrive;   // zero-init, self-resetting
__device__ unsigned g_bar_depart;

__device__ __forceinline__ ull ffma2(ull a, ull b, ull c)
{
    ull d;
    asm("fma.rn.f32x2 %0, %1, %2, %3;" : "=l"(d) : "l"(a), "l"(b), "l"(c));
    return d;
}

__global__ __launch_bounds__(THREADS) void conv_fused(const float* __restrict__ x,
                                                      const float* __restrict__ w,
                                                      float* __restrict__ out)
{
    __shared__ float2     sInd[CI][ROWS][10];  // dup pairs (f_u,f_u), u=0..8, [9]=pad. 35840 B
    __shared__ ulonglong2 sWa[CI][32];         // (w0_k,w0_k32),(w1_k,w1_k32)        16384 B
    __shared__ ull        sWb[CI][32];         // (w2_k,w2_k32)                       8192 B

    const int tid   = threadIdx.x;
    const int kb    = blockIdx.x;          // 0..7
    const int s     = blockIdx.y;          // 0..15
    const int k0    = kb * TK;
    const int iBase = s * CI;

    // ---- zero-pad entries u in {0,8,9} (disjoint from value writes) ----
    for (int e = tid; e < CI * ROWS * 3; e += THREADS) {
        int i = e / (ROWS * 3);
        int r = e - i * (ROWS * 3);
        int row = r / 3;
        int z = r - row * 3;                    // 0,1,2 -> u = 0,8,9
        int u = (z == 0) ? 0 : (7 + z);
        sInd[i][row][u] = make_float2(0.f, 0.f);
    }

    // ---- stage input slab, width roll baked in, duplicated pairs ----
    for (int e = tid; e < 2 * CI * 49; e += THREADS) {
        int o  = e / (CI * 49);
        int r  = e - o * (CI * 49);
        int i  = r / 49;
        int p  = r - i * 49;
        int n  = p / 7;
        int mw = p - n * 7;
        float v = x[(o * 512 + iBase + i) * 49 + p];
        int m = mw + 1; if (m == 7) m = 0;      // width roll +1
        sInd[i][o * 7 + n][m + 1] = make_float2(v, v);   // f[u] = r[u-1]
    }

    // ---- stage weight pairs: lane kl owns (k0+kl, k0+32+kl) ----
    for (int e = tid; e < CI * 32 * 3; e += THREADS) {
        int i  = e / (32 * 3);
        int q  = e - i * (32 * 3);
        int kl = q / 3;
        int j  = q - kl * 3;
        float wa = w[(iBase + i) * 1536 + (k0 + kl) * 3 + j];
        float wb = w[(iBase + i) * 1536 + (k0 + 32 + kl) * 3 + j];
        if (j == 2) {
            float2 p2 = make_float2(wa, wb);
            sWb[i][kl] = *reinterpret_cast<ull*>(&p2);
        } else {
            float* dst = reinterpret_cast<float*>(&sWa[i][kl]);
            dst[j * 2 + 0] = wa;
            dst[j * 2 + 1] = wb;
        }
    }

    __syncthreads();

    // ---- compute: warp = (row, i-half); lane = k-pair ----
    const int warp = tid >> 5;       // 0..27
    const int lane = tid & 31;
    const int row  = warp >> 1;      // 0..13 = o*7+n
    const int half = warp & 1;
    const int o    = row / 7;
    const int n    = row - o * 7;
    const int i0   = half * CIH;

    ull A[7];
#pragma unroll
    for (int m = 0; m < 7; m++) A[m] = 0ull;

#pragma unroll 4
    for (int ii = 0; ii < CIH; ii++) {
        const int i = i0 + ii;
        const ulonglong2* pr = reinterpret_cast<const ulonglong2*>(&sInd[i][row][0]);
        ulonglong2 L0 = pr[0];   // p0,p1   (broadcast LDS.128)
        ulonglong2 L1 = pr[1];   // p2,p3
        ulonglong2 L2 = pr[2];   // p4,p5
        ulonglong2 L3 = pr[3];   // p6,p7
        ulonglong2 L4 = pr[4];   // p8,pad
        ulonglong2 W01 = sWa[i][lane];
        ull        W2  = sWb[i][lane];
        ull p0 = L0.x, p1 = L0.y, p2 = L1.x, p3 = L1.y;
        ull p4 = L2.x, p5 = L2.y, p6 = L3.x, p7 = L3.y, p8 = L4.x;

        // A[m] += p[m]*w0 + p[m+1]*w1 + p[m+2]*w2
        A[0] = ffma2(p0, W01.x, A[0]); A[0] = ffma2(p1, W01.y, A[0]); A[0] = ffma2(p2, W2, A[0]);
        A[1] = ffma2(p1, W01.x, A[1]); A[1] = ffma2(p2, W01.y, A[1]); A[1] = ffma2(p3, W2, A[1]);
        A[2] = ffma2(p2, W01.x, A[2]); A[2] = ffma2(p3, W01.y, A[2]); A[2] = ffma2(p4, W2, A[2]);
        A[3] = ffma2(p3, W01.x, A[3]); A[3] = ffma2(p4, W01.y, A[3]); A[3] = ffma2(p5, W2, A[3]);
        A[4] = ffma2(p4, W01.x, A[4]); A[4] = ffma2(p5, W01.y, A[4]); A[4] = ffma2(p6, W2, A[4]);
        A[5] = ffma2(p5, W01.x, A[5]); A[5] = ffma2(p6, W01.y, A[5]); A[5] = ffma2(p7, W2, A[5]);
        A[6] = ffma2(p6, W01.x, A[6]); A[6] = ffma2(p7, W01.y, A[6]); A[6] = ffma2(p8, W2, A[6]);
    }

    // ---- intra-block half-merge via smem (overlay on dead sInd) ----
    float2* red = reinterpret_cast<float2*>(&sInd[0][0][0]);  // need 25088 B <= 35840 B
    __syncthreads();                       // mainloop done; sInd reusable
    if (half == 1) {
#pragma unroll
        for (int m = 0; m < 7; m++)
            red[(row * 32 + lane) * 7 + m] = *reinterpret_cast<float2*>(&A[m]);
    }
    __syncthreads();

    if (half == 0) {
        int nOut = n + 1; if (nOut == 7) nOut = 0;   // height roll +1
        float2* dst = &g_scr[((((s * 2 + o) * NKT + kb) * 32 + lane) * 49) + nOut * 7];
#pragma unroll
        for (int m = 0; m < 7; m++) {
            float2 a = *reinterpret_cast<float2*>(&A[m]);
            float2 b = red[(row * 32 + lane) * 7 + m];
            a.x += b.x; a.y += b.y;
            dst[m] = a;
        }
    }

    // ---- grid-wide barrier (128 blocks, all co-resident) ----
    __threadfence();
    __syncthreads();
    if (tid == 0) {
        atomicAdd(&g_bar_arrive, 1u);
        while (*(volatile unsigned*)&g_bar_arrive < NBLOCKS) __nanosleep(64);
    }
    __syncthreads();

    // ---- distributed reduce: 25088 entries of (o,kc,kl,q), each -> 2 outputs ----
    int gid = blockIdx.y * (NKT * THREADS) + blockIdx.x * THREADS + tid;
    if (gid < 2 * NKT * 32 * 49) {
        int q  = gid % 49;
        int r  = gid / 49;
        int kl = r & 31;  r >>= 5;
        int kc = r & (NKT - 1);
        int oo = r >> 3;
        float2 sum = make_float2(0.f, 0.f);
#pragma unroll
        for (int sp = 0; sp < S_SPLITS; sp++) {
            float2 v = __ldcg(&g_scr[((((sp * 2 + oo) * NKT + kc) * 32 + kl) * 49) + q]);
            sum.x += v.x; sum.y += v.y;
        }
        int c = oo * 512 + kc * TK + kl;
        out[c * 49 + q]        = sum.x;
        out[(c + 32) * 49 + q] = sum.y;
    }

    // ---- reset barrier for next graph replay ----
    __syncthreads();
    if (tid == 0) {
        unsigned t = atomicAdd(&g_bar_depart, 1u);
        if (t == NBLOCKS - 1) {
            g_bar_arrive = 0;
            __threadfence();
            g_bar_depart = 0;
        }
    }
}

extern "C" void kernel_launch(void* const* d_in, const int* in_sizes, int n_in,
                              void* d_out, int out_size)
{
    const float* x = (const float*)d_in[0];
    const float* w = (const float*)d_in[1];
    float* out = (float*)d_out;

    conv_fused<<<dim3(NKT, S_SPLITS), THREADS>>>(x, w, out);
}